// round 2
// baseline (speedup 1.0000x reference)
#include <cuda_runtime.h>
#include <cuda_bf16.h>

// NT-Xent loss, B=4096, C=128 -> 2B=8192 rows.
// Fused: normalize -> (GEMM + exp + row-sum, no sim materialization) -> log-reduce.

#define NROWS 8192
#define CDIM  128
#define INV_T 2.0f   // 1 / TEMPERATURE (0.5)

// Scratch (device globals; no allocations allowed in kernel_launch).
__device__ float g_normT[CDIM * NROWS];   // k-major: g_normT[k*NROWS + i]
__device__ float g_rowsum[2 * NROWS];     // per-column-half partial exp-sums
__device__ float g_pos[NROWS];            // sim(i, partner(i)) / T

// ---------------------------------------------------------------------------
// Kernel 1: row L2-normalize, write transposed (k-major) normalized matrix.
// One thread per row. 8192 threads.
// ---------------------------------------------------------------------------
__global__ void norm_kernel(const float* __restrict__ zi,
                            const float* __restrict__ zj) {
    int i = blockIdx.x * blockDim.x + threadIdx.x;
    if (i >= NROWS) return;
    const float* src = (i < NROWS / 2) ? (zi + (size_t)i * CDIM)
                                       : (zj + (size_t)(i - NROWS / 2) * CDIM);
    float ss = 0.0f;
#pragma unroll
    for (int k4 = 0; k4 < CDIM / 4; k4++) {
        float4 v = *reinterpret_cast<const float4*>(src + k4 * 4);
        ss += v.x * v.x + v.y * v.y + v.z * v.z + v.w * v.w;
    }
    float rinv = rsqrtf(ss);
#pragma unroll
    for (int k4 = 0; k4 < CDIM / 4; k4++) {
        float4 v = *reinterpret_cast<const float4*>(src + k4 * 4);
        g_normT[(k4 * 4 + 0) * NROWS + i] = v.x * rinv;
        g_normT[(k4 * 4 + 1) * NROWS + i] = v.y * rinv;
        g_normT[(k4 * 4 + 2) * NROWS + i] = v.z * rinv;
        g_normT[(k4 * 4 + 3) * NROWS + i] = v.w * rinv;
    }
}

// ---------------------------------------------------------------------------
// Kernel 2: fused sim-GEMM + exp + row-sum.
// Grid: (64 row tiles, 2 column halves). Block: 256 threads.
// Each block: rows [bx*128, bx*128+128), loops over 32 column tiles of 128.
// Microtile: 8x8 per thread (16x16 thread grid).
// Smem (dynamic, 128KB): As[k][128], Bs[k][128] (k-major -> broadcast A reads).
// ---------------------------------------------------------------------------
__global__ void __launch_bounds__(256, 1)
simexp_kernel() {
    extern __shared__ float sm[];
    float* As = sm;                 // [128][128] k-major: As[k*128 + r]
    float* Bs = sm + 128 * 128;     // [128][128] k-major: Bs[k*128 + c]

    const int tid = threadIdx.x;
    const int tx = tid & 15;        // column group 0..15
    const int ty = tid >> 4;        // row group 0..15
    const int rowbase = blockIdx.x * 128;
    const int half = blockIdx.y;    // column half: cols [half*4096, half*4096+4096)

    // Load A tile once: As[k][r] = g_normT[k][rowbase + r]
    for (int it = tid; it < 128 * 32; it += 256) {
        int k = it >> 5;
        int c4 = (it & 31) * 4;
        float4 v = *reinterpret_cast<const float4*>(
            &g_normT[(size_t)k * NROWS + rowbase + c4]);
        *reinterpret_cast<float4*>(&As[k * 128 + c4]) = v;
    }

    float racc[8];
#pragma unroll
    for (int r = 0; r < 8; r++) racc[r] = 0.0f;

    for (int ct = 0; ct < 32; ct++) {
        const int colbase = half * 4096 + ct * 128;

        __syncthreads();  // previous Bs fully consumed
        for (int it = tid; it < 128 * 32; it += 256) {
            int k = it >> 5;
            int c4 = (it & 31) * 4;
            float4 v = *reinterpret_cast<const float4*>(
                &g_normT[(size_t)k * NROWS + colbase + c4]);
            *reinterpret_cast<float4*>(&Bs[k * 128 + c4]) = v;
        }
        __syncthreads();

        float acc[8][8];
#pragma unroll
        for (int r = 0; r < 8; r++)
#pragma unroll
            for (int c = 0; c < 8; c++) acc[r][c] = 0.0f;

#pragma unroll 8
        for (int k = 0; k < 128; k++) {
            float av[8], bv[8];
            *reinterpret_cast<float4*>(&av[0]) =
                *reinterpret_cast<const float4*>(&As[k * 128 + ty * 8]);
            *reinterpret_cast<float4*>(&av[4]) =
                *reinterpret_cast<const float4*>(&As[k * 128 + ty * 8 + 4]);
            *reinterpret_cast<float4*>(&bv[0]) =
                *reinterpret_cast<const float4*>(&Bs[k * 128 + tx * 8]);
            *reinterpret_cast<float4*>(&bv[4]) =
                *reinterpret_cast<const float4*>(&Bs[k * 128 + tx * 8 + 4]);
#pragma unroll
            for (int r = 0; r < 8; r++)
#pragma unroll
                for (int c = 0; c < 8; c++)
                    acc[r][c] = fmaf(av[r], bv[c], acc[r][c]);
        }

        // Epilogue: scale by 1/T, exp, accumulate row sums (skip diagonal),
        // capture positive-pair logit.
#pragma unroll
        for (int r = 0; r < 8; r++) {
            const int gr = rowbase + ty * 8 + r;
            const int partner = (gr + 4096) & (NROWS - 1);
            float rs = 0.0f;
#pragma unroll
            for (int c = 0; c < 8; c++) {
                const int gc = colbase + tx * 8 + c;
                float s = acc[r][c] * INV_T;
                float e = __expf(s);
                rs += (gr != gc) ? e : 0.0f;
                if (gc == partner) g_pos[gr] = s;
            }
            racc[r] += rs;
        }
    }

    // Reduce racc across the 16 tx-threads of each row (reuse As as scratch).
    __syncthreads();
#pragma unroll
    for (int r = 0; r < 8; r++) sm[(ty * 8 + r) * 16 + tx] = racc[r];
    __syncthreads();
    if (tid < 128) {
        float s = 0.0f;
#pragma unroll
        for (int t = 0; t < 16; t++) s += sm[tid * 16 + t];
        g_rowsum[half * NROWS + rowbase + tid] = s;
    }
}

// ---------------------------------------------------------------------------
// Kernel 3: per-row loss + mean. Single block.
// loss_i = log(S_i + exp(p_i)) - p_i   (S_i excludes diagonal, includes the
// positive-pair sim once; the prepended pos column adds exp(p_i) again).
// ---------------------------------------------------------------------------
__global__ void loss_kernel(float* __restrict__ out) {
    const int tid = threadIdx.x;
    float lsum = 0.0f;
    for (int i = tid; i < NROWS; i += 256) {
        float S = g_rowsum[i] + g_rowsum[NROWS + i];
        float p = g_pos[i];
        lsum += logf(S + expf(p)) - p;
    }
    __shared__ float red[256];
    red[tid] = lsum;
    __syncthreads();
    for (int s = 128; s > 0; s >>= 1) {
        if (tid < s) red[tid] += red[tid + s];
        __syncthreads();
    }
    if (tid == 0) out[0] = red[0] * (1.0f / (float)NROWS);
}

// ---------------------------------------------------------------------------
extern "C" void kernel_launch(void* const* d_in, const int* in_sizes, int n_in,
                              void* d_out, int out_size) {
    const float* zi = (const float*)d_in[0];
    const float* zj = (const float*)d_in[1];
    float* out = (float*)d_out;

    norm_kernel<<<NROWS / 256, 256>>>(zi, zj);

    cudaFuncSetAttribute(simexp_kernel,
                         cudaFuncAttributeMaxDynamicSharedMemorySize,
                         128 * 128 * 2 * sizeof(float));
    simexp_kernel<<<dim3(64, 2), 256, 128 * 128 * 2 * sizeof(float)>>>();

    loss_kernel<<<1, 256>>>(out);
}

// round 6
// speedup vs baseline: 5.9735x; 5.9735x over previous
#include <cuda_runtime.h>
#include <cuda_bf16.h>
#include <cstdint>

// NT-Xent loss, B=4096, C=128 -> 8192 rows; sim = N N^T never materialized.
// R4: warp-level mma.sync (bf16 HMMA, portable PTX - compute_103-safe),
// register-resident accumulators, fused exp + row-sum epilogue.

#define NROWS 8192
#define HALFN 4096
#define CDIM  128
// exp(2*x) = 2^(x * 2*log2(e))
#define EXP_SCALE 2.8853900817779268f

// Scratch (device globals; no allocations allowed anywhere).
__device__ __align__(16) __nv_bfloat16 g_norm[NROWS * CDIM];  // row-major bf16
__device__ float g_part[64 * NROWS];   // per-column-tile partial exp row sums
__device__ float g_pos[NROWS];         // positive-pair logit p_i
__device__ float g_bsum[64];           // per-block loss partials

// Smem tile geometry: 128 rows x 128 bf16, row stride 136 bf16 (272 B) so
// ldmatrix 8-row phases hit distinct 16B bank groups (272 % 128 = 16).
#define ROWB   272
#define ATILE  (128 * ROWB)      // 34816 B
#define SMEM_BYTES (2 * ATILE)   // 69632 B

__device__ __forceinline__ uint32_t smem_u32(const void* p) {
    uint32_t a;
    asm("{ .reg .u64 t; cvta.to.shared.u64 t, %1; cvt.u32.u64 %0, t; }"
        : "=r"(a) : "l"(p));
    return a;
}

#define LDSM4(r, addr)                                                   \
    asm volatile("ldmatrix.sync.aligned.m8n8.x4.shared.b16 "             \
                 "{%0,%1,%2,%3}, [%4];"                                  \
                 : "=r"((r)[0]), "=r"((r)[1]), "=r"((r)[2]), "=r"((r)[3])\
                 : "r"(addr))

#define MMA16816(c, a, b0, b1)                                           \
    asm volatile("mma.sync.aligned.m16n8k16.row.col.f32.bf16.bf16.f32 "  \
                 "{%0,%1,%2,%3}, {%4,%5,%6,%7}, {%8,%9}, {%0,%1,%2,%3};" \
                 : "+f"((c)[0]), "+f"((c)[1]), "+f"((c)[2]), "+f"((c)[3])\
                 : "r"((a)[0]), "r"((a)[1]), "r"((a)[2]), "r"((a)[3]),   \
                   "r"(b0), "r"(b1))

// ---------------------------------------------------------------------------
// Kernel 1: one warp per row - L2 normalize, emit row-major bf16.
// ---------------------------------------------------------------------------
__global__ void norm_kernel(const float* __restrict__ zi,
                            const float* __restrict__ zj) {
    int warp = (blockIdx.x * blockDim.x + threadIdx.x) >> 5;
    int lane = threadIdx.x & 31;
    if (warp >= NROWS) return;
    const float* src = (warp < HALFN) ? (zi + (size_t)warp * CDIM)
                                      : (zj + (size_t)(warp - HALFN) * CDIM);
    float4 v = reinterpret_cast<const float4*>(src)[lane];
    float ss = v.x * v.x + v.y * v.y + v.z * v.z + v.w * v.w;
#pragma unroll
    for (int o = 16; o; o >>= 1) ss += __shfl_xor_sync(0xFFFFFFFFu, ss, o);
    float rinv = rsqrtf(ss);
    __nv_bfloat162 a = __floats2bfloat162_rn(v.x * rinv, v.y * rinv);
    __nv_bfloat162 b = __floats2bfloat162_rn(v.z * rinv, v.w * rinv);
    uint2 pk;
    pk.x = *reinterpret_cast<uint32_t*>(&a);
    pk.y = *reinterpret_cast<uint32_t*>(&b);
    reinterpret_cast<uint2*>(g_norm + (size_t)warp * CDIM)[lane] = pk;
}

// ---------------------------------------------------------------------------
// Epilogue helper: exp + row-sum over this thread's 4x4 grid of acc tiles.
// CHECK path zeroes the diagonal element and captures the positive logit.
// Writes per-(row, n-warp) partials into the smem reduction buffer.
// ---------------------------------------------------------------------------
template <bool CHECK>
__device__ __forceinline__ void epilogue(float acc[4][4][4], float* red,
                                         int rowbase, int colbase,
                                         int wm, int wn, int lane) {
#pragma unroll
    for (int mt = 0; mt < 4; mt++) {
        const int r0 = wm * 64 + mt * 16 + (lane >> 2);   // local row
        const int gr0 = rowbase + r0;
        const int gr1 = gr0 + 8;
        const int p0 = (gr0 + HALFN) & (NROWS - 1);
        const int p1 = (gr1 + HALFN) & (NROWS - 1);
        float rs0 = 0.0f, rs1 = 0.0f;
#pragma unroll
        for (int nt = 0; nt < 4; nt++) {
            const int gc = colbase + wn * 32 + nt * 8 + (lane & 3) * 2;
            float v0 = acc[mt][nt][0], v1 = acc[mt][nt][1];
            float v2 = acc[mt][nt][2], v3 = acc[mt][nt][3];
            float e0 = exp2f(v0 * EXP_SCALE);
            float e1 = exp2f(v1 * EXP_SCALE);
            float e2 = exp2f(v2 * EXP_SCALE);
            float e3 = exp2f(v3 * EXP_SCALE);
            if (CHECK) {
                if (gc + 0 == gr0) e0 = 0.0f;
                if (gc + 1 == gr0) e1 = 0.0f;
                if (gc + 0 == gr1) e2 = 0.0f;
                if (gc + 1 == gr1) e3 = 0.0f;
                if (gc + 0 == p0) g_pos[gr0] = 2.0f * v0;
                if (gc + 1 == p0) g_pos[gr0] = 2.0f * v1;
                if (gc + 0 == p1) g_pos[gr1] = 2.0f * v2;
                if (gc + 1 == p1) g_pos[gr1] = 2.0f * v3;
            }
            rs0 += e0 + e1;
            rs1 += e2 + e3;
        }
        // reduce across the 4 lanes sharing each row
        rs0 += __shfl_xor_sync(0xFFFFFFFFu, rs0, 1);
        rs0 += __shfl_xor_sync(0xFFFFFFFFu, rs0, 2);
        rs1 += __shfl_xor_sync(0xFFFFFFFFu, rs1, 1);
        rs1 += __shfl_xor_sync(0xFFFFFFFFu, rs1, 2);
        if ((lane & 3) == 0) {
            red[r0 * 4 + wn] = rs0;
            red[(r0 + 8) * 4 + wn] = rs1;
        }
    }
}

// ---------------------------------------------------------------------------
// Kernel 2: 128x128x128 bf16 mma.sync tile, fused exp + row-sum.
// Grid (64, 64), 256 threads (8 warps, 2m x 4n; warp tile 64x32).
// ---------------------------------------------------------------------------
__global__ void __launch_bounds__(256)
simexp_mma() {
    extern __shared__ char smem[];
    char* sA = smem;
    char* sB = smem + ATILE;
    const int tid = threadIdx.x;
    const int wid = tid >> 5;
    const int lane = tid & 31;
    const int wm = wid >> 2;
    const int wn = wid & 3;
    const int rowbase = blockIdx.x * 128;
    const int colbase = blockIdx.y * 128;

    // Load A (rows) and B (cols-as-rows) tiles: 4096 uint4 total.
    const uint4* gsrc = reinterpret_cast<const uint4*>(g_norm);
#pragma unroll
    for (int i = 0; i < 16; i++) {
        const int idx = tid + i * 256;
        const bool isA = idx < 2048;
        const int local = isA ? idx : idx - 2048;
        const int row = local >> 4;
        const int ch = local & 15;
        const int grow = (isA ? rowbase : colbase) + row;
        uint4 v = gsrc[(size_t)grow * 16 + ch];
        *reinterpret_cast<uint4*>((isA ? sA : sB) + row * ROWB + ch * 16) = v;
    }
    __syncthreads();

    // Per-lane ldmatrix base addresses.
    const uint32_t aBase = smem_u32(sA)
        + (wm * 64 + (lane & 15)) * ROWB + (lane >> 4) * 16;
    const uint32_t bBase = smem_u32(sB)
        + (wn * 32 + (lane & 7) + ((lane >> 4) & 1) * 8) * ROWB
        + ((lane >> 3) & 1) * 16;

    float acc[4][4][4];
#pragma unroll
    for (int mt = 0; mt < 4; mt++)
#pragma unroll
        for (int nt = 0; nt < 4; nt++)
#pragma unroll
            for (int c = 0; c < 4; c++) acc[mt][nt][c] = 0.0f;

#pragma unroll
    for (int ks = 0; ks < 8; ks++) {
        uint32_t a[4][4];
#pragma unroll
        for (int mt = 0; mt < 4; mt++)
            LDSM4(a[mt], aBase + mt * 16 * ROWB + ks * 32);
        uint32_t b[2][4];   // each x4 = two n-tiles' {b0,b1}
#pragma unroll
        for (int np = 0; np < 2; np++)
            LDSM4(b[np], bBase + np * 16 * ROWB + ks * 32);
#pragma unroll
        for (int mt = 0; mt < 4; mt++)
#pragma unroll
            for (int nt = 0; nt < 4; nt++)
                MMA16816(acc[mt][nt], a[mt],
                         b[nt >> 1][(nt & 1) * 2], b[nt >> 1][(nt & 1) * 2 + 1]);
    }

    __syncthreads();           // done reading tiles; reuse sA for reduction
    float* red = reinterpret_cast<float*>(sA);   // [128][4]

    const bool hasdiag = (blockIdx.x == blockIdx.y);
    const bool haspos = (blockIdx.y == ((blockIdx.x + 32) & 63));
    if (hasdiag || haspos)
        epilogue<true>(acc, red, rowbase, colbase, wm, wn, lane);
    else
        epilogue<false>(acc, red, rowbase, colbase, wm, wn, lane);

    __syncthreads();
    if (tid < 128) {
        float s = red[tid * 4 + 0] + red[tid * 4 + 1]
                + red[tid * 4 + 2] + red[tid * 4 + 3];
        g_part[(size_t)blockIdx.y * NROWS + rowbase + tid] = s;
    }
}

// ---------------------------------------------------------------------------
// Kernel 3a: per-row loss, 64 blocks x 128 rows, block-reduce to g_bsum.
// loss_i = log(S_i + exp(p_i)) - p_i
// ---------------------------------------------------------------------------
__global__ void loss_a() {
    const int tid = threadIdx.x;
    const int i = blockIdx.x * 128 + tid;
    float S = 0.0f;
#pragma unroll
    for (int t = 0; t < 64; t++) S += g_part[(size_t)t * NROWS + i];
    const float p = g_pos[i];
    float li = logf(S + __expf(p)) - p;
    __shared__ float red[128];
    red[tid] = li;
    __syncthreads();
    for (int s = 64; s > 0; s >>= 1) {
        if (tid < s) red[tid] += red[tid + s];
        __syncthreads();
    }
    if (tid == 0) g_bsum[blockIdx.x] = red[0];
}

// Kernel 3b: final mean over 64 block partials.
__global__ void loss_b(float* __restrict__ out) {
    const int lane = threadIdx.x;
    float s = g_bsum[lane] + g_bsum[lane + 32];
#pragma unroll
    for (int o = 16; o; o >>= 1) s += __shfl_xor_sync(0xFFFFFFFFu, s, o);
    if (lane == 0) out[0] = s * (1.0f / (float)NROWS);
}

// ---------------------------------------------------------------------------
extern "C" void kernel_launch(void* const* d_in, const int* in_sizes, int n_in,
                              void* d_out, int out_size) {
    const float* zi = (const float*)d_in[0];
    const float* zj = (const float*)d_in[1];
    float* out = (float*)d_out;

    norm_kernel<<<NROWS * 32 / 256, 256>>>(zi, zj);

    cudaFuncSetAttribute(simexp_mma,
                         cudaFuncAttributeMaxDynamicSharedMemorySize,
                         SMEM_BYTES);
    simexp_mma<<<dim3(64, 64), 256, SMEM_BYTES>>>();

    loss_a<<<64, 128>>>();
    loss_b<<<1, 32>>>(out);
}

// round 9
// speedup vs baseline: 7.9265x; 1.3269x over previous
#include <cuda_runtime.h>
#include <cuda_bf16.h>
#include <cstdint>

// NT-Xent loss, B=4096, C=128 -> 8192 rows; sim = N N^T never materialized.
// R6: symmetry-halved HMMA (each off-diag 128x128 block yields BOTH row sums
// and column sums of exp(sim/T)), 2080 active CTAs instead of 4096, fused
// single-kernel loss reduction (deterministic last-block pattern).

#define NROWS 8192
#define HALFN 4096
#define CDIM  128
// exp(2*x) = 2^(x * 2*log2(e))
#define EXP_SCALE 2.8853900817779268f

// Scratch (device globals; no allocations allowed anywhere).
__device__ __align__(16) __nv_bfloat16 g_norm[NROWS * CDIM];  // row-major bf16
__device__ float g_part[64 * NROWS];   // per-tile-slot partial exp row sums
__device__ float g_pos[NROWS];         // positive-pair logit p_i
__device__ float g_bsum[64];           // per-block loss partials
__device__ unsigned g_ctr;             // last-block election counter

// Smem tile geometry: 128 rows x 128 bf16, row stride 136 bf16 (272 B) so
// ldmatrix 8-row phases hit distinct 16B bank groups (272 % 128 = 16).
#define ROWB   272
#define ATILE  (128 * ROWB)      // 34816 B
#define SMEM_BYTES (2 * ATILE)   // 69632 B

__device__ __forceinline__ uint32_t smem_u32(const void* p) {
    uint32_t a;
    asm("{ .reg .u64 t; cvta.to.shared.u64 t, %1; cvt.u32.u64 %0, t; }"
        : "=r"(a) : "l"(p));
    return a;
}

#define LDSM4(r, addr)                                                   \
    asm volatile("ldmatrix.sync.aligned.m8n8.x4.shared.b16 "             \
                 "{%0,%1,%2,%3}, [%4];"                                  \
                 : "=r"((r)[0]), "=r"((r)[1]), "=r"((r)[2]), "=r"((r)[3])\
                 : "r"(addr))

#define MMA16816(c, a, b0, b1)                                           \
    asm volatile("mma.sync.aligned.m16n8k16.row.col.f32.bf16.bf16.f32 "  \
                 "{%0,%1,%2,%3}, {%4,%5,%6,%7}, {%8,%9}, {%0,%1,%2,%3};" \
                 : "+f"((c)[0]), "+f"((c)[1]), "+f"((c)[2]), "+f"((c)[3])\
                 : "r"((a)[0]), "r"((a)[1]), "r"((a)[2]), "r"((a)[3]),   \
                   "r"(b0), "r"(b1))

// ---------------------------------------------------------------------------
// Kernel 1: one warp per row - L2 normalize, emit row-major bf16.
// ---------------------------------------------------------------------------
__global__ void norm_kernel(const float* __restrict__ zi,
                            const float* __restrict__ zj) {
    int warp = (blockIdx.x * blockDim.x + threadIdx.x) >> 5;
    int lane = threadIdx.x & 31;
    if (warp >= NROWS) return;
    const float* src = (warp < HALFN) ? (zi + (size_t)warp * CDIM)
                                      : (zj + (size_t)(warp - HALFN) * CDIM);
    float4 v = reinterpret_cast<const float4*>(src)[lane];
    float ss = v.x * v.x + v.y * v.y + v.z * v.z + v.w * v.w;
#pragma unroll
    for (int o = 16; o; o >>= 1) ss += __shfl_xor_sync(0xFFFFFFFFu, ss, o);
    float rinv = rsqrtf(ss);
    __nv_bfloat162 a = __floats2bfloat162_rn(v.x * rinv, v.y * rinv);
    __nv_bfloat162 b = __floats2bfloat162_rn(v.z * rinv, v.w * rinv);
    uint2 pk;
    pk.x = *reinterpret_cast<uint32_t*>(&a);
    pk.y = *reinterpret_cast<uint32_t*>(&b);
    reinterpret_cast<uint2*>(g_norm + (size_t)warp * CDIM)[lane] = pk;
}

// ---------------------------------------------------------------------------
// Epilogue: exp + BOTH row sums and column sums over the 4x4 acc grid.
// CHECK handles diagonal zeroing (d==0 blocks) and positive-pair capture
// (d==32 blocks; writes g_pos for both row index and column index - the same
// sim element serves both directions by symmetry).
// redR: [128][4] per-(row, wn) partials.  redC: [128][2] per-(col, wm).
// ---------------------------------------------------------------------------
template <bool CHECK>
__device__ __forceinline__ void epilogue(float acc[4][4][4], float* redR,
                                         float* redC, int rowbase, int colbase,
                                         int wm, int wn, int lane) {
    float csum[4][2];
#pragma unroll
    for (int nt = 0; nt < 4; nt++) csum[nt][0] = csum[nt][1] = 0.0f;

#pragma unroll
    for (int mt = 0; mt < 4; mt++) {
        const int r0 = wm * 64 + mt * 16 + (lane >> 2);   // local row
        const int gr0 = rowbase + r0;
        const int gr1 = gr0 + 8;
        const int p0 = (gr0 + HALFN) & (NROWS - 1);
        const int p1 = (gr1 + HALFN) & (NROWS - 1);
        float rs0 = 0.0f, rs1 = 0.0f;
#pragma unroll
        for (int nt = 0; nt < 4; nt++) {
            const int gc = colbase + wn * 32 + nt * 8 + (lane & 3) * 2;
            float v0 = acc[mt][nt][0], v1 = acc[mt][nt][1];
            float v2 = acc[mt][nt][2], v3 = acc[mt][nt][3];
            float e0 = exp2f(v0 * EXP_SCALE);
            float e1 = exp2f(v1 * EXP_SCALE);
            float e2 = exp2f(v2 * EXP_SCALE);
            float e3 = exp2f(v3 * EXP_SCALE);
            if (CHECK) {
                if (gc + 0 == gr0) e0 = 0.0f;          // diagonal (d==0)
                if (gc + 1 == gr0) e1 = 0.0f;
                if (gc + 0 == gr1) e2 = 0.0f;
                if (gc + 1 == gr1) e3 = 0.0f;
                if (gc + 0 == p0) { g_pos[gr0] = 2.0f * v0; g_pos[gc + 0] = 2.0f * v0; }
                if (gc + 1 == p0) { g_pos[gr0] = 2.0f * v1; g_pos[gc + 1] = 2.0f * v1; }
                if (gc + 0 == p1) { g_pos[gr1] = 2.0f * v2; g_pos[gc + 0] = 2.0f * v2; }
                if (gc + 1 == p1) { g_pos[gr1] = 2.0f * v3; g_pos[gc + 1] = 2.0f * v3; }
            }
            rs0 += e0 + e1;
            rs1 += e2 + e3;
            csum[nt][0] += e0 + e2;
            csum[nt][1] += e1 + e3;
        }
        // reduce rows across the 4 lanes sharing each row
        rs0 += __shfl_xor_sync(0xFFFFFFFFu, rs0, 1);
        rs0 += __shfl_xor_sync(0xFFFFFFFFu, rs0, 2);
        rs1 += __shfl_xor_sync(0xFFFFFFFFu, rs1, 1);
        rs1 += __shfl_xor_sync(0xFFFFFFFFu, rs1, 2);
        if ((lane & 3) == 0) {
            redR[r0 * 4 + wn] = rs0;
            redR[(r0 + 8) * 4 + wn] = rs1;
        }
    }

    // reduce columns across the 8 lanes sharing each column (same lane&3)
#pragma unroll
    for (int nt = 0; nt < 4; nt++)
#pragma unroll
        for (int c = 0; c < 2; c++) {
            float s = csum[nt][c];
            s += __shfl_xor_sync(0xFFFFFFFFu, s, 4);
            s += __shfl_xor_sync(0xFFFFFFFFu, s, 8);
            s += __shfl_xor_sync(0xFFFFFFFFu, s, 16);
            csum[nt][c] = s;
        }
    if (lane < 4) {
#pragma unroll
        for (int nt = 0; nt < 4; nt++)
#pragma unroll
            for (int c = 0; c < 2; c++)
                redC[(wn * 32 + nt * 8 + lane * 2 + c) * 2 + wm] = csum[nt][c];
    }
}

// ---------------------------------------------------------------------------
// Kernel 2: one CTA per unordered tile pair. Grid (64, 33):
//   bx = blockIdx.x, d = blockIdx.y, by = (bx+d)&63; d==32 only for bx<32.
// Covers every unordered {bx,by} exactly once (2080 active CTAs).
// Writes rowsums -> g_part[by][bx-rows]; colsums -> g_part[bx][by-rows]
// (skipped for d==0 to avoid double count). Unique writer per slot.
// ---------------------------------------------------------------------------
__global__ void __launch_bounds__(256)
simexp_mma() {
    const int bx = blockIdx.x;
    const int d = blockIdx.y;
    if (d == 32 && bx >= 32) return;
    const int by = (bx + d) & 63;

    extern __shared__ char smem[];
    char* sA = smem;
    char* sB = smem + ATILE;
    const int tid = threadIdx.x;
    const int wid = tid >> 5;
    const int lane = tid & 31;
    const int wm = wid >> 2;
    const int wn = wid & 3;
    const int rowbase = bx * 128;
    const int colbase = by * 128;

    // Load A (bx rows) and B (by rows) tiles: 4096 uint4 total.
    const uint4* gsrc = reinterpret_cast<const uint4*>(g_norm);
#pragma unroll
    for (int i = 0; i < 16; i++) {
        const int idx = tid + i * 256;
        const bool isA = idx < 2048;
        const int local = isA ? idx : idx - 2048;
        const int row = local >> 4;
        const int ch = local & 15;
        const int grow = (isA ? rowbase : colbase) + row;
        uint4 v = gsrc[(size_t)grow * 16 + ch];
        *reinterpret_cast<uint4*>((isA ? sA : sB) + row * ROWB + ch * 16) = v;
    }
    __syncthreads();

    // Per-lane ldmatrix base addresses.
    const uint32_t aBase = smem_u32(sA)
        + (wm * 64 + (lane & 15)) * ROWB + (lane >> 4) * 16;
    const uint32_t bBase = smem_u32(sB)
        + (wn * 32 + (lane & 7) + ((lane >> 4) & 1) * 8) * ROWB
        + ((lane >> 3) & 1) * 16;

    float acc[4][4][4];
#pragma unroll
    for (int mt = 0; mt < 4; mt++)
#pragma unroll
        for (int nt = 0; nt < 4; nt++)
#pragma unroll
            for (int c = 0; c < 4; c++) acc[mt][nt][c] = 0.0f;

#pragma unroll
    for (int ks = 0; ks < 8; ks++) {
        uint32_t a[4][4];
#pragma unroll
        for (int mt = 0; mt < 4; mt++)
            LDSM4(a[mt], aBase + mt * 16 * ROWB + ks * 32);
        uint32_t b[2][4];   // each x4 = two n-tiles' {b0,b1}
#pragma unroll
        for (int np = 0; np < 2; np++)
            LDSM4(b[np], bBase + np * 16 * ROWB + ks * 32);
#pragma unroll
        for (int mt = 0; mt < 4; mt++)
#pragma unroll
            for (int nt = 0; nt < 4; nt++)
                MMA16816(acc[mt][nt], a[mt],
                         b[nt >> 1][(nt & 1) * 2], b[nt >> 1][(nt & 1) * 2 + 1]);
    }

    __syncthreads();           // tiles consumed; reuse sA for reductions
    float* redR = reinterpret_cast<float*>(sA);          // [128][4]
    float* redC = reinterpret_cast<float*>(sA + 2048);   // [128][2]

    if (d == 0 || d == 32)
        epilogue<true>(acc, redR, redC, rowbase, colbase, wm, wn, lane);
    else
        epilogue<false>(acc, redR, redC, rowbase, colbase, wm, wn, lane);

    __syncthreads();
    if (tid < 128) {
        float rs = redR[tid * 4 + 0] + redR[tid * 4 + 1]
                 + redR[tid * 4 + 2] + redR[tid * 4 + 3];
        g_part[(size_t)by * NROWS + rowbase + tid] = rs;
        if (d != 0) {
            float cs = redC[tid * 2 + 0] + redC[tid * 2 + 1];
            g_part[(size_t)bx * NROWS + colbase + tid] = cs;
        }
    }
}

// ---------------------------------------------------------------------------
// Kernel 3: per-row loss + fused final mean (deterministic last-block).
// loss_i = log(S_i + exp(p_i)) - p_i
// ---------------------------------------------------------------------------
__global__ void loss_kernel(float* __restrict__ out) {
    const int tid = threadIdx.x;
    const int i = blockIdx.x * 128 + tid;
    float S = 0.0f;
#pragma unroll
    for (int t = 0; t < 64; t++) S += g_part[(size_t)t * NROWS + i];
    const float p = g_pos[i];
    float li = logf(S + __expf(p)) - p;
    __shared__ float red[128];
    __shared__ bool last;
    red[tid] = li;
    __syncthreads();
    for (int s = 64; s > 0; s >>= 1) {
        if (tid < s) red[tid] += red[tid + s];
        __syncthreads();
    }
    if (tid == 0) {
        g_bsum[blockIdx.x] = red[0];
        __threadfence();
        last = (atomicAdd(&g_ctr, 1u) == 63u);
    }
    __syncthreads();
    if (last && tid < 32) {
        float s = g_bsum[tid] + g_bsum[tid + 32];
#pragma unroll
        for (int o = 16; o; o >>= 1) s += __shfl_xor_sync(0xFFFFFFFFu, s, o);
        if (tid == 0) {
            out[0] = s * (1.0f / (float)NROWS);
            g_ctr = 0;   // reset for the next (graph-replayed) call
        }
    }
}

// ---------------------------------------------------------------------------
extern "C" void kernel_launch(void* const* d_in, const int* in_sizes, int n_in,
                              void* d_out, int out_size) {
    const float* zi = (const float*)d_in[0];
    const float* zj = (const float*)d_in[1];
    float* out = (float*)d_out;

    norm_kernel<<<NROWS * 32 / 256, 256>>>(zi, zj);

    cudaFuncSetAttribute(simexp_mma,
                         cudaFuncAttributeMaxDynamicSharedMemorySize,
                         SMEM_BYTES);
    simexp_mma<<<dim3(64, 33), 256, SMEM_BYTES>>>();

    loss_kernel<<<64, 128>>>(out);
}

// round 10
// speedup vs baseline: 9.0126x; 1.1370x over previous
#include <cuda_runtime.h>
#include <cuda_bf16.h>
#include <cstdint>

// NT-Xent loss, B=4096, C=128 -> 8192 rows; sim = N N^T never materialized.
// R9: force 2 CTAs/SM on the HMMA kernel (__launch_bounds__(256,2) -> 128-reg
// cap) so 16 warps/SM hide L2 + ldsm latency; norm kernel at MLP=2.

#define NROWS 8192
#define HALFN 4096
#define CDIM  128
// exp(2*x) = 2^(x * 2*log2(e))
#define EXP_SCALE 2.8853900817779268f

// Scratch (device globals; no allocations allowed anywhere).
__device__ __align__(16) __nv_bfloat16 g_norm[NROWS * CDIM];  // row-major bf16
__device__ float g_part[64 * NROWS];   // per-tile-slot partial exp row sums
__device__ float g_pos[NROWS];         // positive-pair logit p_i
__device__ float g_bsum[64];           // per-block loss partials
__device__ unsigned g_ctr;             // last-block election counter

// Smem tile geometry: 128 rows x 128 bf16, row stride 136 bf16 (272 B) so
// ldmatrix 8-row phases hit distinct 16B bank groups (272 % 128 = 16).
#define ROWB   272
#define ATILE  (128 * ROWB)      // 34816 B
#define SMEM_BYTES (2 * ATILE)   // 69632 B

__device__ __forceinline__ uint32_t smem_u32(const void* p) {
    uint32_t a;
    asm("{ .reg .u64 t; cvta.to.shared.u64 t, %1; cvt.u32.u64 %0, t; }"
        : "=r"(a) : "l"(p));
    return a;
}

#define LDSM4(r, addr)                                                   \
    asm volatile("ldmatrix.sync.aligned.m8n8.x4.shared.b16 "             \
                 "{%0,%1,%2,%3}, [%4];"                                  \
                 : "=r"((r)[0]), "=r"((r)[1]), "=r"((r)[2]), "=r"((r)[3])\
                 : "r"(addr))

#define MMA16816(c, a, b0, b1)                                           \
    asm volatile("mma.sync.aligned.m16n8k16.row.col.f32.bf16.bf16.f32 "  \
                 "{%0,%1,%2,%3}, {%4,%5,%6,%7}, {%8,%9}, {%0,%1,%2,%3};" \
                 : "+f"((c)[0]), "+f"((c)[1]), "+f"((c)[2]), "+f"((c)[3])\
                 : "r"((a)[0]), "r"((a)[1]), "r"((a)[2]), "r"((a)[3]),   \
                   "r"(b0), "r"(b1))

// ---------------------------------------------------------------------------
// Kernel 1: two rows per warp (16 lanes each), 2 float4 loads per thread
// (MLP=2), half-warp shuffle reduce, emit row-major bf16.
// ---------------------------------------------------------------------------
__global__ void norm_kernel(const float* __restrict__ zi,
                            const float* __restrict__ zj) {
    const int w = (blockIdx.x * blockDim.x + threadIdx.x) >> 5;
    const int lane = threadIdx.x & 31;
    const int r = 2 * w + (lane >> 4);
    const int l16 = lane & 15;
    if (r >= NROWS) return;
    const float* src = (r < HALFN) ? (zi + (size_t)r * CDIM)
                                   : (zj + (size_t)(r - HALFN) * CDIM);
    float4 v0 = reinterpret_cast<const float4*>(src)[l16];
    float4 v1 = reinterpret_cast<const float4*>(src)[l16 + 16];
    float ss = v0.x * v0.x + v0.y * v0.y + v0.z * v0.z + v0.w * v0.w
             + v1.x * v1.x + v1.y * v1.y + v1.z * v1.z + v1.w * v1.w;
#pragma unroll
    for (int o = 8; o; o >>= 1) ss += __shfl_xor_sync(0xFFFFFFFFu, ss, o);
    float rinv = rsqrtf(ss);
    __nv_bfloat162 a0 = __floats2bfloat162_rn(v0.x * rinv, v0.y * rinv);
    __nv_bfloat162 b0 = __floats2bfloat162_rn(v0.z * rinv, v0.w * rinv);
    __nv_bfloat162 a1 = __floats2bfloat162_rn(v1.x * rinv, v1.y * rinv);
    __nv_bfloat162 b1 = __floats2bfloat162_rn(v1.z * rinv, v1.w * rinv);
    uint2 p0, p1;
    p0.x = *reinterpret_cast<uint32_t*>(&a0);
    p0.y = *reinterpret_cast<uint32_t*>(&b0);
    p1.x = *reinterpret_cast<uint32_t*>(&a1);
    p1.y = *reinterpret_cast<uint32_t*>(&b1);
    uint2* dst = reinterpret_cast<uint2*>(g_norm + (size_t)r * CDIM);
    dst[l16] = p0;
    dst[l16 + 16] = p1;
}

// ---------------------------------------------------------------------------
// Epilogue: exp + BOTH row sums and column sums over the 4x4 acc grid.
// CHECK handles diagonal zeroing (d==0 blocks) and positive-pair capture
// (d==32 blocks; the same sim element serves both directions by symmetry).
// redR: [128][4] per-(row, wn) partials.  redC: [128][2] per-(col, wm).
// ---------------------------------------------------------------------------
template <bool CHECK>
__device__ __forceinline__ void epilogue(float acc[4][4][4], float* redR,
                                         float* redC, int rowbase, int colbase,
                                         int wm, int wn, int lane) {
    float csum[4][2];
#pragma unroll
    for (int nt = 0; nt < 4; nt++) csum[nt][0] = csum[nt][1] = 0.0f;

#pragma unroll
    for (int mt = 0; mt < 4; mt++) {
        const int r0 = wm * 64 + mt * 16 + (lane >> 2);   // local row
        const int gr0 = rowbase + r0;
        const int gr1 = gr0 + 8;
        const int p0 = (gr0 + HALFN) & (NROWS - 1);
        const int p1 = (gr1 + HALFN) & (NROWS - 1);
        float rs0 = 0.0f, rs1 = 0.0f;
#pragma unroll
        for (int nt = 0; nt < 4; nt++) {
            const int gc = colbase + wn * 32 + nt * 8 + (lane & 3) * 2;
            float v0 = acc[mt][nt][0], v1 = acc[mt][nt][1];
            float v2 = acc[mt][nt][2], v3 = acc[mt][nt][3];
            float e0 = exp2f(v0 * EXP_SCALE);
            float e1 = exp2f(v1 * EXP_SCALE);
            float e2 = exp2f(v2 * EXP_SCALE);
            float e3 = exp2f(v3 * EXP_SCALE);
            if (CHECK) {
                if (gc + 0 == gr0) e0 = 0.0f;          // diagonal (d==0)
                if (gc + 1 == gr0) e1 = 0.0f;
                if (gc + 0 == gr1) e2 = 0.0f;
                if (gc + 1 == gr1) e3 = 0.0f;
                if (gc + 0 == p0) { g_pos[gr0] = 2.0f * v0; g_pos[gc + 0] = 2.0f * v0; }
                if (gc + 1 == p0) { g_pos[gr0] = 2.0f * v1; g_pos[gc + 1] = 2.0f * v1; }
                if (gc + 0 == p1) { g_pos[gr1] = 2.0f * v2; g_pos[gc + 0] = 2.0f * v2; }
                if (gc + 1 == p1) { g_pos[gr1] = 2.0f * v3; g_pos[gc + 1] = 2.0f * v3; }
            }
            rs0 += e0 + e1;
            rs1 += e2 + e3;
            csum[nt][0] += e0 + e2;
            csum[nt][1] += e1 + e3;
        }
        // reduce rows across the 4 lanes sharing each row
        rs0 += __shfl_xor_sync(0xFFFFFFFFu, rs0, 1);
        rs0 += __shfl_xor_sync(0xFFFFFFFFu, rs0, 2);
        rs1 += __shfl_xor_sync(0xFFFFFFFFu, rs1, 1);
        rs1 += __shfl_xor_sync(0xFFFFFFFFu, rs1, 2);
        if ((lane & 3) == 0) {
            redR[r0 * 4 + wn] = rs0;
            redR[(r0 + 8) * 4 + wn] = rs1;
        }
    }

    // reduce columns across the 8 lanes sharing each column (same lane&3)
#pragma unroll
    for (int nt = 0; nt < 4; nt++)
#pragma unroll
        for (int c = 0; c < 2; c++) {
            float s = csum[nt][c];
            s += __shfl_xor_sync(0xFFFFFFFFu, s, 4);
            s += __shfl_xor_sync(0xFFFFFFFFu, s, 8);
            s += __shfl_xor_sync(0xFFFFFFFFu, s, 16);
            csum[nt][c] = s;
        }
    if (lane < 4) {
#pragma unroll
        for (int nt = 0; nt < 4; nt++)
#pragma unroll
            for (int c = 0; c < 2; c++)
                redC[(wn * 32 + nt * 8 + lane * 2 + c) * 2 + wm] = csum[nt][c];
    }
}

// ---------------------------------------------------------------------------
// Kernel 2: one CTA per unordered tile pair. Grid (64, 33):
//   bx = blockIdx.x, d = blockIdx.y, by = (bx+d)&63; d==32 only for bx<32.
// Covers every unordered {bx,by} exactly once (2080 active CTAs).
// Writes rowsums -> g_part[by][bx-rows]; colsums -> g_part[bx][by-rows]
// (skipped for d==0 to avoid double count). Unique writer per slot.
// __launch_bounds__(256, 2): cap at 128 regs so 2 CTAs co-reside per SM.
// ---------------------------------------------------------------------------
__global__ void __launch_bounds__(256, 2)
simexp_mma() {
    const int bx = blockIdx.x;
    const int d = blockIdx.y;
    if (d == 32 && bx >= 32) return;
    const int by = (bx + d) & 63;

    extern __shared__ char smem[];
    char* sA = smem;
    char* sB = smem + ATILE;
    const int tid = threadIdx.x;
    const int wid = tid >> 5;
    const int lane = tid & 31;
    const int wm = wid >> 2;
    const int wn = wid & 3;
    const int rowbase = bx * 128;
    const int colbase = by * 128;

    // Load A (bx rows) and B (by rows) tiles: 4096 uint4 total.
    const uint4* gsrc = reinterpret_cast<const uint4*>(g_norm);
#pragma unroll
    for (int i = 0; i < 16; i++) {
        const int idx = tid + i * 256;
        const bool isA = idx < 2048;
        const int local = isA ? idx : idx - 2048;
        const int row = local >> 4;
        const int ch = local & 15;
        const int grow = (isA ? rowbase : colbase) + row;
        uint4 v = gsrc[(size_t)grow * 16 + ch];
        *reinterpret_cast<uint4*>((isA ? sA : sB) + row * ROWB + ch * 16) = v;
    }
    __syncthreads();

    // Per-lane ldmatrix base addresses.
    const uint32_t aBase = smem_u32(sA)
        + (wm * 64 + (lane & 15)) * ROWB + (lane >> 4) * 16;
    const uint32_t bBase = smem_u32(sB)
        + (wn * 32 + (lane & 7) + ((lane >> 4) & 1) * 8) * ROWB
        + ((lane >> 3) & 1) * 16;

    float acc[4][4][4];
#pragma unroll
    for (int mt = 0; mt < 4; mt++)
#pragma unroll
        for (int nt = 0; nt < 4; nt++)
#pragma unroll
            for (int c = 0; c < 4; c++) acc[mt][nt][c] = 0.0f;

#pragma unroll
    for (int ks = 0; ks < 8; ks++) {
        uint32_t a[4][4];
#pragma unroll
        for (int mt = 0; mt < 4; mt++)
            LDSM4(a[mt], aBase + mt * 16 * ROWB + ks * 32);
        uint32_t b[2][4];   // each x4 = two n-tiles' {b0,b1}
#pragma unroll
        for (int np = 0; np < 2; np++)
            LDSM4(b[np], bBase + np * 16 * ROWB + ks * 32);
#pragma unroll
        for (int mt = 0; mt < 4; mt++)
#pragma unroll
            for (int nt = 0; nt < 4; nt++)
                MMA16816(acc[mt][nt], a[mt],
                         b[nt >> 1][(nt & 1) * 2], b[nt >> 1][(nt & 1) * 2 + 1]);
    }

    __syncthreads();           // tiles consumed; reuse sA for reductions
    float* redR = reinterpret_cast<float*>(sA);          // [128][4]
    float* redC = reinterpret_cast<float*>(sA + 2048);   // [128][2]

    if (d == 0 || d == 32)
        epilogue<true>(acc, redR, redC, rowbase, colbase, wm, wn, lane);
    else
        epilogue<false>(acc, redR, redC, rowbase, colbase, wm, wn, lane);

    __syncthreads();
    if (tid < 128) {
        float rs = redR[tid * 4 + 0] + redR[tid * 4 + 1]
                 + redR[tid * 4 + 2] + redR[tid * 4 + 3];
        g_part[(size_t)by * NROWS + rowbase + tid] = rs;
        if (d != 0) {
            float cs = redC[tid * 2 + 0] + redC[tid * 2 + 1];
            g_part[(size_t)bx * NROWS + colbase + tid] = cs;
        }
    }
}

// ---------------------------------------------------------------------------
// Kernel 3: per-row loss + fused final mean (deterministic last-block).
// loss_i = log(S_i + exp(p_i)) - p_i
// ---------------------------------------------------------------------------
__global__ void loss_kernel(float* __restrict__ out) {
    const int tid = threadIdx.x;
    const int i = blockIdx.x * 128 + tid;
    float S = 0.0f;
#pragma unroll
    for (int t = 0; t < 64; t++) S += g_part[(size_t)t * NROWS + i];
    const float p = g_pos[i];
    float li = logf(S + __expf(p)) - p;
    __shared__ float red[128];
    __shared__ bool last;
    red[tid] = li;
    __syncthreads();
    for (int s = 64; s > 0; s >>= 1) {
        if (tid < s) red[tid] += red[tid + s];
        __syncthreads();
    }
    if (tid == 0) {
        g_bsum[blockIdx.x] = red[0];
        __threadfence();
        last = (atomicAdd(&g_ctr, 1u) == 63u);
    }
    __syncthreads();
    if (last && tid < 32) {
        float s = g_bsum[tid] + g_bsum[tid + 32];
#pragma unroll
        for (int o = 16; o; o >>= 1) s += __shfl_xor_sync(0xFFFFFFFFu, s, o);
        if (tid == 0) {
            out[0] = s * (1.0f / (float)NROWS);
            g_ctr = 0;   // reset for the next (graph-replayed) call
        }
    }
}

// ---------------------------------------------------------------------------
extern "C" void kernel_launch(void* const* d_in, const int* in_sizes, int n_in,
                              void* d_out, int out_size) {
    const float* zi = (const float*)d_in[0];
    const float* zj = (const float*)d_in[1];
    float* out = (float*)d_out;

    norm_kernel<<<NROWS * 32 / 2 / 256, 256>>>(zi, zj);

    cudaFuncSetAttribute(simexp_mma,
                         cudaFuncAttributeMaxDynamicSharedMemorySize,
                         SMEM_BYTES);
    simexp_mma<<<dim3(64, 33), 256, SMEM_BYTES>>>();

    loss_kernel<<<64, 128>>>(out);
}

// round 12
// speedup vs baseline: 9.4371x; 1.0471x over previous
#include <cuda_runtime.h>
#include <cuda_bf16.h>
#include <cstdint>

// NT-Xent loss, B=4096, C=128 -> 8192 rows; sim = N N^T never materialized.
// R10: cp.async two-stage K pipeline in the HMMA kernel (overlap k-half-1
// load with k-half-0 MMA); norm kernel at MLP=4.

#define NROWS 8192
#define HALFN 4096
#define CDIM  128
// exp(2*x) = 2^(x * 2*log2(e))
#define EXP_SCALE 2.8853900817779268f

// Scratch (device globals; no allocations allowed anywhere).
__device__ __align__(16) __nv_bfloat16 g_norm[NROWS * CDIM];  // row-major bf16
__device__ float g_part[64 * NROWS];   // per-tile-slot partial exp row sums
__device__ float g_pos[NROWS];         // positive-pair logit p_i
__device__ float g_bsum[64];           // per-block loss partials
__device__ unsigned g_ctr;             // last-block election counter

// Smem tile geometry: 128 rows x 128 bf16, row stride 136 bf16 (272 B) so
// ldmatrix 8-row phases hit distinct 16B bank groups (272 % 128 = 16).
#define ROWB   272
#define ATILE  (128 * ROWB)      // 34816 B
#define SMEM_BYTES (2 * ATILE)   // 69632 B

__device__ __forceinline__ uint32_t smem_u32(const void* p) {
    uint32_t a;
    asm("{ .reg .u64 t; cvta.to.shared.u64 t, %1; cvt.u32.u64 %0, t; }"
        : "=r"(a) : "l"(p));
    return a;
}

#define LDSM4(r, addr)                                                   \
    asm volatile("ldmatrix.sync.aligned.m8n8.x4.shared.b16 "             \
                 "{%0,%1,%2,%3}, [%4];"                                  \
                 : "=r"((r)[0]), "=r"((r)[1]), "=r"((r)[2]), "=r"((r)[3])\
                 : "r"(addr))

#define MMA16816(c, a, b0, b1)                                           \
    asm volatile("mma.sync.aligned.m16n8k16.row.col.f32.bf16.bf16.f32 "  \
                 "{%0,%1,%2,%3}, {%4,%5,%6,%7}, {%8,%9}, {%0,%1,%2,%3};" \
                 : "+f"((c)[0]), "+f"((c)[1]), "+f"((c)[2]), "+f"((c)[3])\
                 : "r"((a)[0]), "r"((a)[1]), "r"((a)[2]), "r"((a)[3]),   \
                   "r"(b0), "r"(b1))

#define CP_ASYNC16(saddr, gptr)                                          \
    asm volatile("cp.async.cg.shared.global [%0], [%1], 16;"             \
                 :: "r"(saddr), "l"(gptr))
#define CP_COMMIT() asm volatile("cp.async.commit_group;" ::: "memory")
#define CP_WAIT(n)  asm volatile("cp.async.wait_group %0;" :: "n"(n) : "memory")

// ---------------------------------------------------------------------------
// Kernel 1: four rows per warp (8 lanes each), 4 independent float4 loads per
// thread (MLP=4), 8-lane shuffle reduce, emit row-major bf16.
// ---------------------------------------------------------------------------
__global__ void norm_kernel(const float* __restrict__ zi,
                            const float* __restrict__ zj) {
    const int w = (blockIdx.x * blockDim.x + threadIdx.x) >> 5;
    const int lane = threadIdx.x & 31;
    const int r = 4 * w + (lane >> 3);
    const int l8 = lane & 7;
    if (r >= NROWS) return;
    const float* src = (r < HALFN) ? (zi + (size_t)r * CDIM)
                                   : (zj + (size_t)(r - HALFN) * CDIM);
    float4 v[4];
#pragma unroll
    for (int j = 0; j < 4; j++)
        v[j] = reinterpret_cast<const float4*>(src)[l8 + 8 * j];
    float ss = 0.0f;
#pragma unroll
    for (int j = 0; j < 4; j++)
        ss += v[j].x * v[j].x + v[j].y * v[j].y + v[j].z * v[j].z + v[j].w * v[j].w;
#pragma unroll
    for (int o = 4; o; o >>= 1) ss += __shfl_xor_sync(0xFFFFFFFFu, ss, o);
    float rinv = rsqrtf(ss);
    uint2* dst = reinterpret_cast<uint2*>(g_norm + (size_t)r * CDIM);
#pragma unroll
    for (int j = 0; j < 4; j++) {
        __nv_bfloat162 a = __floats2bfloat162_rn(v[j].x * rinv, v[j].y * rinv);
        __nv_bfloat162 b = __floats2bfloat162_rn(v[j].z * rinv, v[j].w * rinv);
        uint2 pk;
        pk.x = *reinterpret_cast<uint32_t*>(&a);
        pk.y = *reinterpret_cast<uint32_t*>(&b);
        dst[l8 + 8 * j] = pk;
    }
}

// ---------------------------------------------------------------------------
// Epilogue: exp + BOTH row sums and column sums over the 4x4 acc grid.
// CHECK handles diagonal zeroing (d==0 blocks) and positive-pair capture
// (d==32 blocks; the same sim element serves both directions by symmetry).
// redR: [128][4] per-(row, wn) partials.  redC: [128][2] per-(col, wm).
// ---------------------------------------------------------------------------
template <bool CHECK>
__device__ __forceinline__ void epilogue(float acc[4][4][4], float* redR,
                                         float* redC, int rowbase, int colbase,
                                         int wm, int wn, int lane) {
    float csum[4][2];
#pragma unroll
    for (int nt = 0; nt < 4; nt++) csum[nt][0] = csum[nt][1] = 0.0f;

#pragma unroll
    for (int mt = 0; mt < 4; mt++) {
        const int r0 = wm * 64 + mt * 16 + (lane >> 2);   // local row
        const int gr0 = rowbase + r0;
        const int gr1 = gr0 + 8;
        const int p0 = (gr0 + HALFN) & (NROWS - 1);
        const int p1 = (gr1 + HALFN) & (NROWS - 1);
        float rs0 = 0.0f, rs1 = 0.0f;
#pragma unroll
        for (int nt = 0; nt < 4; nt++) {
            const int gc = colbase + wn * 32 + nt * 8 + (lane & 3) * 2;
            float v0 = acc[mt][nt][0], v1 = acc[mt][nt][1];
            float v2 = acc[mt][nt][2], v3 = acc[mt][nt][3];
            float e0 = exp2f(v0 * EXP_SCALE);
            float e1 = exp2f(v1 * EXP_SCALE);
            float e2 = exp2f(v2 * EXP_SCALE);
            float e3 = exp2f(v3 * EXP_SCALE);
            if (CHECK) {
                if (gc + 0 == gr0) e0 = 0.0f;          // diagonal (d==0)
                if (gc + 1 == gr0) e1 = 0.0f;
                if (gc + 0 == gr1) e2 = 0.0f;
                if (gc + 1 == gr1) e3 = 0.0f;
                if (gc + 0 == p0) { g_pos[gr0] = 2.0f * v0; g_pos[gc + 0] = 2.0f * v0; }
                if (gc + 1 == p0) { g_pos[gr0] = 2.0f * v1; g_pos[gc + 1] = 2.0f * v1; }
                if (gc + 0 == p1) { g_pos[gr1] = 2.0f * v2; g_pos[gc + 0] = 2.0f * v2; }
                if (gc + 1 == p1) { g_pos[gr1] = 2.0f * v3; g_pos[gc + 1] = 2.0f * v3; }
            }
            rs0 += e0 + e1;
            rs1 += e2 + e3;
            csum[nt][0] += e0 + e2;
            csum[nt][1] += e1 + e3;
        }
        // reduce rows across the 4 lanes sharing each row
        rs0 += __shfl_xor_sync(0xFFFFFFFFu, rs0, 1);
        rs0 += __shfl_xor_sync(0xFFFFFFFFu, rs0, 2);
        rs1 += __shfl_xor_sync(0xFFFFFFFFu, rs1, 1);
        rs1 += __shfl_xor_sync(0xFFFFFFFFu, rs1, 2);
        if ((lane & 3) == 0) {
            redR[r0 * 4 + wn] = rs0;
            redR[(r0 + 8) * 4 + wn] = rs1;
        }
    }

    // reduce columns across the 8 lanes sharing each column (same lane&3)
#pragma unroll
    for (int nt = 0; nt < 4; nt++)
#pragma unroll
        for (int c = 0; c < 2; c++) {
            float s = csum[nt][c];
            s += __shfl_xor_sync(0xFFFFFFFFu, s, 4);
            s += __shfl_xor_sync(0xFFFFFFFFu, s, 8);
            s += __shfl_xor_sync(0xFFFFFFFFu, s, 16);
            csum[nt][c] = s;
        }
    if (lane < 4) {
#pragma unroll
        for (int nt = 0; nt < 4; nt++)
#pragma unroll
            for (int c = 0; c < 2; c++)
                redC[(wn * 32 + nt * 8 + lane * 2 + c) * 2 + wm] = csum[nt][c];
    }
}

// ---------------------------------------------------------------------------
// Kernel 2: one CTA per unordered tile pair. Grid (64, 33):
//   bx = blockIdx.x, d = blockIdx.y, by = (bx+d)&63; d==32 only for bx<32.
// cp.async two-stage pipeline: K-half 0 and K-half 1 issued as separate
// commit groups; MMA on half 0 overlaps the half-1 fetch.
// __launch_bounds__(256, 2): cap at 128 regs so 2 CTAs co-reside per SM.
// ---------------------------------------------------------------------------
__global__ void __launch_bounds__(256, 2)
simexp_mma() {
    const int bx = blockIdx.x;
    const int d = blockIdx.y;
    if (d == 32 && bx >= 32) return;
    const int by = (bx + d) & 63;

    extern __shared__ char smem[];
    char* sA = smem;
    char* sB = smem + ATILE;
    const int tid = threadIdx.x;
    const int wid = tid >> 5;
    const int lane = tid & 31;
    const int wm = wid >> 2;
    const int wn = wid & 3;
    const int rowbase = bx * 128;
    const int colbase = by * 128;

    const uint32_t sAu = smem_u32(sA);
    const uint32_t sBu = smem_u32(sB);
    const uint4* gsrc = reinterpret_cast<const uint4*>(g_norm);

    // Two cp.async groups: half h covers 16B chunks ch = h*8 .. h*8+7
    // (K columns h*64 .. h*64+63) of both the A and B tiles.
#pragma unroll
    for (int h = 0; h < 2; h++) {
#pragma unroll
        for (int i = 0; i < 8; i++) {
            const int idx = tid + i * 256;        // 0..2047
            const bool isA = idx < 1024;
            const int local = idx & 1023;
            const int row = local >> 3;
            const int ch = (local & 7) + h * 8;
            const int grow = (isA ? rowbase : colbase) + row;
            const uint32_t saddr = (isA ? sAu : sBu) + row * ROWB + ch * 16;
            CP_ASYNC16(saddr, gsrc + (size_t)grow * 16 + ch);
        }
        CP_COMMIT();
    }

    // Per-lane ldmatrix base addresses.
    const uint32_t aBase = sAu
        + (wm * 64 + (lane & 15)) * ROWB + (lane >> 4) * 16;
    const uint32_t bBase = sBu
        + (wn * 32 + (lane & 7) + ((lane >> 4) & 1) * 8) * ROWB
        + ((lane >> 3) & 1) * 16;

    float acc[4][4][4];
#pragma unroll
    for (int mt = 0; mt < 4; mt++)
#pragma unroll
        for (int nt = 0; nt < 4; nt++)
#pragma unroll
            for (int c = 0; c < 4; c++) acc[mt][nt][c] = 0.0f;

    CP_WAIT(1);               // half 0 landed; half 1 still in flight
    __syncthreads();

#pragma unroll
    for (int ks = 0; ks < 4; ks++) {
        uint32_t a[4][4];
#pragma unroll
        for (int mt = 0; mt < 4; mt++)
            LDSM4(a[mt], aBase + mt * 16 * ROWB + ks * 32);
        uint32_t b[2][4];
#pragma unroll
        for (int np = 0; np < 2; np++)
            LDSM4(b[np], bBase + np * 16 * ROWB + ks * 32);
#pragma unroll
        for (int mt = 0; mt < 4; mt++)
#pragma unroll
            for (int nt = 0; nt < 4; nt++)
                MMA16816(acc[mt][nt], a[mt],
                         b[nt >> 1][(nt & 1) * 2], b[nt >> 1][(nt & 1) * 2 + 1]);
    }

    CP_WAIT(0);               // half 1 landed
    __syncthreads();

#pragma unroll
    for (int ks = 4; ks < 8; ks++) {
        uint32_t a[4][4];
#pragma unroll
        for (int mt = 0; mt < 4; mt++)
            LDSM4(a[mt], aBase + mt * 16 * ROWB + ks * 32);
        uint32_t b[2][4];
#pragma unroll
        for (int np = 0; np < 2; np++)
            LDSM4(b[np], bBase + np * 16 * ROWB + ks * 32);
#pragma unroll
        for (int mt = 0; mt < 4; mt++)
#pragma unroll
            for (int nt = 0; nt < 4; nt++)
                MMA16816(acc[mt][nt], a[mt],
                         b[nt >> 1][(nt & 1) * 2], b[nt >> 1][(nt & 1) * 2 + 1]);
    }

    __syncthreads();           // tiles consumed; reuse sA for reductions
    float* redR = reinterpret_cast<float*>(sA);          // [128][4]
    float* redC = reinterpret_cast<float*>(sA + 2048);   // [128][2]

    if (d == 0 || d == 32)
        epilogue<true>(acc, redR, redC, rowbase, colbase, wm, wn, lane);
    else
        epilogue<false>(acc, redR, redC, rowbase, colbase, wm, wn, lane);

    __syncthreads();
    if (tid < 128) {
        float rs = redR[tid * 4 + 0] + redR[tid * 4 + 1]
                 + redR[tid * 4 + 2] + redR[tid * 4 + 3];
        g_part[(size_t)by * NROWS + rowbase + tid] = rs;
        if (d != 0) {
            float cs = redC[tid * 2 + 0] + redC[tid * 2 + 1];
            g_part[(size_t)bx * NROWS + colbase + tid] = cs;
        }
    }
}

// ---------------------------------------------------------------------------
// Kernel 3: per-row loss + fused final mean (deterministic last-block).
// loss_i = log(S_i + exp(p_i)) - p_i
// ---------------------------------------------------------------------------
__global__ void loss_kernel(float* __restrict__ out) {
    const int tid = threadIdx.x;
    const int i = blockIdx.x * 128 + tid;
    float S = 0.0f;
#pragma unroll
    for (int t = 0; t < 64; t++) S += g_part[(size_t)t * NROWS + i];
    const float p = g_pos[i];
    float li = logf(S + __expf(p)) - p;
    __shared__ float red[128];
    __shared__ bool last;
    red[tid] = li;
    __syncthreads();
    for (int s = 64; s > 0; s >>= 1) {
        if (tid < s) red[tid] += red[tid + s];
        __syncthreads();
    }
    if (tid == 0) {
        g_bsum[blockIdx.x] = red[0];
        __threadfence();
        last = (atomicAdd(&g_ctr, 1u) == 63u);
    }
    __syncthreads();
    if (last && tid < 32) {
        float s = g_bsum[tid] + g_bsum[tid + 32];
#pragma unroll
        for (int o = 16; o; o >>= 1) s += __shfl_xor_sync(0xFFFFFFFFu, s, o);
        if (tid == 0) {
            out[0] = s * (1.0f / (float)NROWS);
            g_ctr = 0;   // reset for the next (graph-replayed) call
        }
    }
}

// ---------------------------------------------------------------------------
extern "C" void kernel_launch(void* const* d_in, const int* in_sizes, int n_in,
                              void* d_out, int out_size) {
    const float* zi = (const float*)d_in[0];
    const float* zj = (const float*)d_in[1];
    float* out = (float*)d_out;

    norm_kernel<<<NROWS / 4 / 8, 256>>>(zi, zj);

    cudaFuncSetAttribute(simexp_mma,
                         cudaFuncAttributeMaxDynamicSharedMemorySize,
                         SMEM_BYTES);
    simexp_mma<<<dim3(64, 33), 256, SMEM_BYTES>>>();

    loss_kernel<<<64, 128>>>(out);
}